// round 5
// baseline (speedup 1.0000x reference)
#include <cuda_runtime.h>

// SNN layer scan: m_t = 0.9*m + gate*gamma*mw[n] + (0.1*rw[n] - 0.5)*s
//                 s_t = sigmoid(8*(m_t - 0.5)); output s_t for all t.
// One thread owns 4 cells (float4). Double-buffered software pipeline:
// group k+1's 8 LDG.128s are issued BEFORE group k's compute, so every warp
// keeps 8 loads in flight at all times (no memory-idle bubble during compute).

#define GROUP 4   // timesteps per group; pipeline processes 2 groups/iter

__device__ __forceinline__ float fsigmoid(float x) {
    return 1.0f / (1.0f + __expf(-x));  // EX2 + RCP on MUFU
}

struct State {
    float4 m, s;
    float4 mwv;
    float rc_x, rc_y, rc_z, rc_w;
};

__device__ __forceinline__ void load_group(const float4* __restrict__ gptr,
                                           const float4* __restrict__ hptr,
                                           int t0, int bn4,
                                           float4 gb[GROUP], float4 hb[GROUP])
{
    #pragma unroll
    for (int j = 0; j < GROUP; ++j) {
        const size_t off = (size_t)(t0 + j) * bn4;
        gb[j] = __ldcs(gptr + off);
        hb[j] = __ldcs(hptr + off);
    }
}

__device__ __forceinline__ void compute_group(State& st,
                                              const float4 gb[GROUP],
                                              const float4 hb[GROUP],
                                              float4* __restrict__ optr,
                                              int t0, int bn4)
{
    #pragma unroll
    for (int j = 0; j < GROUP; ++j) {
        const float4 g  = gb[j];
        const float4 ga = hb[j];

        st.m.x = fmaf(0.9f, st.m.x, fmaf(g.x * ga.x, st.mwv.x, st.rc_x * st.s.x));
        st.m.y = fmaf(0.9f, st.m.y, fmaf(g.y * ga.y, st.mwv.y, st.rc_y * st.s.y));
        st.m.z = fmaf(0.9f, st.m.z, fmaf(g.z * ga.z, st.mwv.z, st.rc_z * st.s.z));
        st.m.w = fmaf(0.9f, st.m.w, fmaf(g.w * ga.w, st.mwv.w, st.rc_w * st.s.w));

        st.s.x = fsigmoid(fmaf(8.0f, st.m.x, -4.0f));
        st.s.y = fsigmoid(fmaf(8.0f, st.m.y, -4.0f));
        st.s.z = fsigmoid(fmaf(8.0f, st.m.z, -4.0f));
        st.s.w = fsigmoid(fmaf(8.0f, st.m.w, -4.0f));

        __stcs(optr + (size_t)(t0 + j) * bn4, st.s);
    }
}

__global__ __launch_bounds__(256)
void snn_scan_kernel(const float4* __restrict__ m0,
                     const float4* __restrict__ s0,
                     const float4* __restrict__ gate,
                     const float4* __restrict__ gamma,
                     const float4* __restrict__ mw,
                     const float4* __restrict__ rw,
                     float4* __restrict__ out,
                     int T, int bn4, int n4)
{
    const int idx = blockIdx.x * blockDim.x + threadIdx.x;
    if (idx >= bn4) return;

    const int wn = idx % n4;     // flat elem = 4*idx = b*N + n
    State st;
    st.mwv = mw[wn];
    const float4 rwv = rw[wn];
    st.rc_x = fmaf(0.1f, rwv.x, -0.5f);
    st.rc_y = fmaf(0.1f, rwv.y, -0.5f);
    st.rc_z = fmaf(0.1f, rwv.z, -0.5f);
    st.rc_w = fmaf(0.1f, rwv.w, -0.5f);
    st.m = m0[idx];
    st.s = s0[idx];

    const float4* gptr = gate  + idx;
    const float4* hptr = gamma + idx;
    float4*       optr = out   + idx;

    float4 gA[GROUP], hA[GROUP], gB[GROUP], hB[GROUP];

    // T is a multiple of 2*GROUP for the target shape (T=64); handle the
    // pipelined body for the largest multiple-of-8 prefix, tail below.
    const int Tmain = T - (T % (2 * GROUP));

    if (Tmain > 0) {
        load_group(gptr, hptr, 0, bn4, gA, hA);          // prologue: fill A

        for (int t0 = 0; t0 < Tmain; t0 += 2 * GROUP) {
            // prefetch B while A's data is consumed
            if (t0 + GROUP < T) load_group(gptr, hptr, t0 + GROUP, bn4, gB, hB);
            compute_group(st, gA, hA, optr, t0, bn4);

            // prefetch next A while B is consumed
            if (t0 + 2 * GROUP < T) load_group(gptr, hptr, t0 + 2 * GROUP, bn4, gA, hA);
            compute_group(st, gB, hB, optr, t0 + GROUP, bn4);
        }
    }

    // tail (not taken for T=64)
    for (int t = Tmain; t < T; ++t) {
        const size_t off = (size_t)t * bn4;
        const float4 g  = __ldcs(gptr + off);
        const float4 ga = __ldcs(hptr + off);
        st.m.x = fmaf(0.9f, st.m.x, fmaf(g.x * ga.x, st.mwv.x, st.rc_x * st.s.x));
        st.m.y = fmaf(0.9f, st.m.y, fmaf(g.y * ga.y, st.mwv.y, st.rc_y * st.s.y));
        st.m.z = fmaf(0.9f, st.m.z, fmaf(g.z * ga.z, st.mwv.z, st.rc_z * st.s.z));
        st.m.w = fmaf(0.9f, st.m.w, fmaf(g.w * ga.w, st.mwv.w, st.rc_w * st.s.w));
        st.s.x = fsigmoid(fmaf(8.0f, st.m.x, -4.0f));
        st.s.y = fsigmoid(fmaf(8.0f, st.m.y, -4.0f));
        st.s.z = fsigmoid(fmaf(8.0f, st.m.z, -4.0f));
        st.s.w = fsigmoid(fmaf(8.0f, st.m.w, -4.0f));
        __stcs(optr + off, st.s);
    }
}

extern "C" void kernel_launch(void* const* d_in, const int* in_sizes, int n_in,
                              void* d_out, int out_size)
{
    // 0: membrane0 [B,N] f32          1: spikes0 [B,N] f32
    // 2: sinusoidal_gate [T,B,N] f32  3: gamma   [T,B,N] f32
    // 4: membrane_weight [N] f32      5: recurrent_weight [N] f32
    const float4* m0    = (const float4*)d_in[0];
    const float4* s0    = (const float4*)d_in[1];
    const float4* gate  = (const float4*)d_in[2];
    const float4* gamma = (const float4*)d_in[3];
    const float4* mw    = (const float4*)d_in[4];
    const float4* rw    = (const float4*)d_in[5];
    float4* out = (float4*)d_out;

    const int bn  = in_sizes[0];              // B*N elements
    const int n   = in_sizes[4];              // N
    const int T   = in_sizes[2] / bn;         // timesteps (64)
    const int bn4 = bn / 4;
    const int n4  = n / 4;

    const int threads = 256;
    const int blocks  = (bn4 + threads - 1) / threads;   // 512 for default shape
    snn_scan_kernel<<<blocks, threads>>>(m0, s0, gate, gamma, mw, rw, out,
                                         T, bn4, n4);
}

// round 7
// speedup vs baseline: 1.0274x; 1.0274x over previous
#include <cuda_runtime.h>

// SNN layer scan: m_t = 0.9*m + gate*gamma*mw[n] + (0.1*rw[n] - 0.5)*s
//                 s_t = sigmoid(8*(m_t - 0.5)); output s_t for all t.
// One thread owns 4 cells (float4), T in groups of 4 with all 8 group loads
// batched up front (R4 structure — best measured). This round: 128-thread
// blocks -> 1024 CTAs -> ~7 CTAs/SM in one wave, killing the 4-vs-3 CTA
// wave-quantization tail that capped DRAM at 73.7%.

#define GROUP 4

__device__ __forceinline__ float fsigmoid(float x) {
    return 1.0f / (1.0f + __expf(-x));  // EX2 + RCP on MUFU; under HBM floor
}

__global__ __launch_bounds__(128)
void snn_scan_kernel(const float4* __restrict__ m0,
                     const float4* __restrict__ s0,
                     const float4* __restrict__ gate,
                     const float4* __restrict__ gamma,
                     const float4* __restrict__ mw,
                     const float4* __restrict__ rw,
                     float4* __restrict__ out,
                     int T, int bn4, int n4)
{
    const int idx = blockIdx.x * blockDim.x + threadIdx.x;
    if (idx >= bn4) return;

    // flat element = 4*idx = b*N + n; weights index by n only
    const int wn = idx % n4;
    const float4 mwv = mw[wn];
    const float4 rwv = rw[wn];

    // fused recurrent coefficient: (0.1*rw - 0.5) * s
    const float rc_x = fmaf(0.1f, rwv.x, -0.5f);
    const float rc_y = fmaf(0.1f, rwv.y, -0.5f);
    const float rc_z = fmaf(0.1f, rwv.z, -0.5f);
    const float rc_w = fmaf(0.1f, rwv.w, -0.5f);

    float4 m = m0[idx];
    float4 s = s0[idx];

    const float4* gptr = gate  + idx;
    const float4* hptr = gamma + idx;
    float4*       optr = out   + idx;

    float4 gb[GROUP], hb[GROUP];

    for (int t0 = 0; t0 < T; t0 += GROUP) {
        // --- batch ALL group loads first: 8 LDG.128 in flight per warp ---
        #pragma unroll
        for (int j = 0; j < GROUP; ++j) {
            const size_t off = (size_t)(t0 + j) * bn4;
            gb[j] = __ldcs(gptr + off);   // streaming: no reuse, bypass L2 alloc
            hb[j] = __ldcs(hptr + off);
        }

        // --- serial recurrence over the group ---
        #pragma unroll
        for (int j = 0; j < GROUP; ++j) {
            const float4 g  = gb[j];
            const float4 ga = hb[j];

            m.x = fmaf(0.9f, m.x, fmaf(g.x * ga.x, mwv.x, rc_x * s.x));
            m.y = fmaf(0.9f, m.y, fmaf(g.y * ga.y, mwv.y, rc_y * s.y));
            m.z = fmaf(0.9f, m.z, fmaf(g.z * ga.z, mwv.z, rc_z * s.z));
            m.w = fmaf(0.9f, m.w, fmaf(g.w * ga.w, mwv.w, rc_w * s.w));

            s.x = fsigmoid(fmaf(8.0f, m.x, -4.0f));
            s.y = fsigmoid(fmaf(8.0f, m.y, -4.0f));
            s.z = fsigmoid(fmaf(8.0f, m.z, -4.0f));
            s.w = fsigmoid(fmaf(8.0f, m.w, -4.0f));

            __stcs(optr + (size_t)(t0 + j) * bn4, s);  // streaming store
        }
    }
}

extern "C" void kernel_launch(void* const* d_in, const int* in_sizes, int n_in,
                              void* d_out, int out_size)
{
    // 0: membrane0 [B,N] f32          1: spikes0 [B,N] f32
    // 2: sinusoidal_gate [T,B,N] f32  3: gamma   [T,B,N] f32
    // 4: membrane_weight [N] f32      5: recurrent_weight [N] f32
    const float4* m0    = (const float4*)d_in[0];
    const float4* s0    = (const float4*)d_in[1];
    const float4* gate  = (const float4*)d_in[2];
    const float4* gamma = (const float4*)d_in[3];
    const float4* mw    = (const float4*)d_in[4];
    const float4* rw    = (const float4*)d_in[5];
    float4* out = (float4*)d_out;

    const int bn  = in_sizes[0];              // B*N elements
    const int n   = in_sizes[4];              // N
    const int T   = in_sizes[2] / bn;         // timesteps (64)
    const int bn4 = bn / 4;
    const int n4  = n / 4;

    const int threads = 128;                  // finer CTA granularity: 1024 CTAs
    const int blocks  = (bn4 + threads - 1) / threads;
    snn_scan_kernel<<<blocks, threads>>>(m0, s0, gate, gamma, mw, rw, out,
                                         T, bn4, n4);
}